// round 2
// baseline (speedup 1.0000x reference)
#include <cuda_runtime.h>
#include <math.h>

#define C_DIM 1280
#define HW    9216
#define WIMG  96
#define N_ID  16
#define D_IN  512
#define PXB   512          // pixels per block (main kernel)
#define BLKS_PER_BATCH (HW / PXB)   // 18

// ---------------- scratch (no allocations allowed) ----------------
__device__ float g_h[128 * C_DIM];   // GELU hidden of MLP
__device__ float g_p[128 * C_DIM];   // projected (normalized in-place)

// ---------------- f32x2 helpers ----------------
__device__ __forceinline__ unsigned long long fma2(unsigned long long a,
                                                   unsigned long long b,
                                                   unsigned long long c) {
    unsigned long long d;
    asm("fma.rn.f32x2 %0, %1, %2, %3;" : "=l"(d) : "l"(a), "l"(b), "l"(c));
    return d;
}
__device__ __forceinline__ unsigned long long packf2(float lo, float hi) {
    unsigned long long r;
    asm("mov.b64 %0, {%1, %2};" : "=l"(r) : "f"(lo), "f"(hi));
    return r;
}
__device__ __forceinline__ float2 unpackf2(unsigned long long v) {
    float2 r;
    asm("mov.b64 {%0, %1}, %2;" : "=f"(r.x), "=f"(r.y) : "l"(v));
    return r;
}

// ---------------- small GEMM: OUT[M,Nc] = act(A[M,K] @ W[K,Nc] + bias) ----
// tile 32x32, 256 threads, grid (Nc/32, M/32)
__device__ __forceinline__ void gemm32(const float* __restrict__ A,
                                       const float* __restrict__ Wm,
                                       const float* __restrict__ bias,
                                       float* __restrict__ Out,
                                       int K, int Nc, bool dogelu) {
    __shared__ float sA[32][33];
    __shared__ float sB[32][33];
    int t = threadIdx.x;
    int tj = t & 31;
    int tr = t >> 5;                 // 0..7, 4 rows each
    int rowBase = blockIdx.y * 32;
    int colBase = blockIdx.x * 32;
    float acc[4] = {0.f, 0.f, 0.f, 0.f};

    for (int kt = 0; kt < K; kt += 32) {
#pragma unroll
        for (int s = 0; s < 4; s++) {
            int idx = t + s * 256;          // 0..1023
            int r = idx >> 5, kk = idx & 31;
            sA[r][kk] = A[(size_t)(rowBase + r) * K + kt + kk];
            sB[r][kk] = Wm[(size_t)(kt + r) * Nc + colBase + kk];
        }
        __syncthreads();
#pragma unroll
        for (int k = 0; k < 32; k++) {
            float bv = sB[k][tj];
#pragma unroll
            for (int i = 0; i < 4; i++)
                acc[i] = fmaf(sA[tr * 4 + i][k], bv, acc[i]);
        }
        __syncthreads();
    }
#pragma unroll
    for (int i = 0; i < 4; i++) {
        float v = acc[i] + bias[colBase + tj];
        if (dogelu) v = 0.5f * v * (1.f + erff(v * 0.70710678f));
        Out[(size_t)(rowBase + tr * 4 + i) * Nc + colBase + tj] = v;
    }
}

__global__ __launch_bounds__(256) void mlp1_kernel(const float* __restrict__ E,
                                                   const float* __restrict__ W1,
                                                   const float* __restrict__ b1) {
    gemm32(E, W1, b1, g_h, D_IN, C_DIM, true);
}
__global__ __launch_bounds__(256) void mlp2_kernel(const float* __restrict__ W2,
                                                   const float* __restrict__ b2) {
    gemm32(g_h, W2, b2, g_p, C_DIM, C_DIM, false);
}

// ---------------- row-normalize projected: p = p/(||p||+eps)*sqrt(C) ------
__global__ void norm_kernel() {
    int r = blockIdx.x, t = threadIdx.x;
    float* row = g_p + (size_t)r * C_DIM;
    float ss = 0.f;
    for (int c = t; c < C_DIM; c += 128) {
        float v = row[c];
        ss = fmaf(v, v, ss);
    }
#pragma unroll
    for (int o = 16; o > 0; o >>= 1) ss += __shfl_xor_sync(0xffffffffu, ss, o);
    __shared__ float sw[4];
    if ((t & 31) == 0) sw[t >> 5] = ss;
    __syncthreads();
    float tot = sw[0] + sw[1] + sw[2] + sw[3];
    float scale = 35.7770876f / (sqrtf(tot) + 1e-6f);   // sqrt(1280)
    for (int c = t; c < C_DIM; c += 128) row[c] *= scale;
}

// ---------------- main fused kernel ----------------
__global__ __launch_bounds__(256, 1) void main_kernel(const float* __restrict__ hidden,
                                                      const float* __restrict__ bboxes,
                                                      float* __restrict__ out) {
    extern __shared__ float sp[];               // [1280][16] projected (c-major)
    __shared__ int sx1[N_ID], sy1[N_ID], sx2[N_ID], sy2[N_ID], semp[N_ID];

    int t = threadIdx.x;
    int bk = blockIdx.x;
    int b = bk / BLKS_PER_BATCH;
    int pbase = (bk % BLKS_PER_BATCH) * PXB;

    const float* pb = g_p + (size_t)b * (N_ID * C_DIM);
    for (int i = t; i < C_DIM * N_ID; i += 256) {
        int c = i >> 4, n = i & 15;
        sp[i] = pb[n * C_DIM + c];
    }
    if (t < N_ID) {
        float bx1 = bboxes[t * 4 + 0] * 96.f;
        float by1 = bboxes[t * 4 + 1] * 96.f;
        float bx2 = bboxes[t * 4 + 2] * 96.f;
        float by2 = bboxes[t * 4 + 3] * 96.f;
        int X1 = (int)floorf(fminf(fmaxf(bx1, 0.f), 96.f));
        int Y1 = (int)floorf(fminf(fmaxf(by1, 0.f), 96.f));
        int X2 = (int)floorf(fminf(fmaxf(bx2, 0.f), 96.f));
        int Y2 = (int)floorf(fminf(fmaxf(by2, 0.f), 96.f));
        sx1[t] = X1; sy1[t] = Y1; sx2[t] = X2; sy2[t] = Y2;
        semp[t] = (X1 >= X2) || (Y1 >= Y2);
    }
    __syncthreads();

    int allempty = 1;
#pragma unroll
    for (int n = 0; n < N_ID; n++) allempty &= semp[n];

    int px = pbase + 2 * t;                 // even; pair never crosses a row
    int y = px / WIMG;
    int x = px - y * WIMG;
    const float* hp = hidden + (size_t)b * C_DIM * HW + px;

    // ---- pass 1: sumsq + 16 dot products (f32x2, N paired) ----
    unsigned long long acc0[8], acc1[8];
#pragma unroll
    for (int k = 0; k < 8; k++) { acc0[k] = 0ull; acc1[k] = 0ull; }
    float ss0 = 0.f, ss1 = 0.f;

#pragma unroll 8
    for (int c = 0; c < C_DIM; c++) {
        float2 h = *(const float2*)(hp + c * HW);
        ss0 = fmaf(h.x, h.x, ss0);
        ss1 = fmaf(h.y, h.y, ss1);
        unsigned long long hx = packf2(h.x, h.x);
        unsigned long long hy = packf2(h.y, h.y);
        const unsigned long long* p2 = (const unsigned long long*)(sp + (c << 4));
#pragma unroll
        for (int k = 0; k < 8; k++) {
            unsigned long long pv = p2[k];
            acc0[k] = fma2(hx, pv, acc0[k]);
            acc1[k] = fma2(hy, pv, acc1[k]);
        }
    }

    // ---- weights: sigmoid(score/T)*mask, normalize over N, ^1.2 ----
    float w0[N_ID], w1[N_ID];
    float sum0 = 0.f, sum1 = 0.f;
    const float invT = 1.999996f;           // 1/(0.5+1e-6)
    float inv0 = invT / (sqrtf(ss0) + 1e-6f);
    float inv1 = invT / (sqrtf(ss1) + 1e-6f);
#pragma unroll
    for (int k = 0; k < 8; k++) {
        float2 d0 = unpackf2(acc0[k]);
        float2 d1 = unpackf2(acc1[k]);
#pragma unroll
        for (int j = 0; j < 2; j++) {
            int n = 2 * k + j;
            float da = (j == 0) ? d0.x : d0.y;
            float db = (j == 0) ? d1.x : d1.y;
            int ybox = (y >= sy1[n]) & (y < sy2[n]);
            int m0 = allempty | (ybox & (x >= sx1[n]) & (x < sx2[n]));
            int m1 = allempty | (ybox & ((x + 1) >= sx1[n]) & ((x + 1) < sx2[n]));
            float s0v = 1.f / (1.f + __expf(-da * inv0));
            float s1v = 1.f / (1.f + __expf(-db * inv1));
            float wv0 = m0 ? s0v : 0.f;
            float wv1 = m1 ? s1v : 0.f;
            w0[n] = wv0; sum0 += wv0;
            w1[n] = wv1; sum1 += wv1;
        }
    }
    float is0 = 1.f / (sum0 + 1e-6f);
    float is1 = 1.f / (sum1 + 1e-6f);
    unsigned long long wp0[8], wp1[8];
#pragma unroll
    for (int k = 0; k < 8; k++) {
        wp0[k] = packf2(__powf(w0[2 * k] * is0, 1.2f), __powf(w0[2 * k + 1] * is0, 1.2f));
        wp1[k] = packf2(__powf(w1[2 * k] * is1, 1.2f), __powf(w1[2 * k + 1] * is1, 1.2f));
    }

    // ---- pass 2: out = hidden + 1.5 * sum_n w[n]*p[n,c] ----
    float* op = out + (size_t)b * C_DIM * HW + px;
#pragma unroll 8
    for (int c = 0; c < C_DIM; c++) {
        float2 h = *(const float2*)(hp + c * HW);
        const unsigned long long* p2 = (const unsigned long long*)(sp + (c << 4));
        unsigned long long s0 = 0ull, s1 = 0ull;
#pragma unroll
        for (int k = 0; k < 8; k++) {
            unsigned long long pv = p2[k];
            s0 = fma2(wp0[k], pv, s0);
            s1 = fma2(wp1[k], pv, s1);
        }
        float2 a0 = unpackf2(s0), a1 = unpackf2(s1);
        float2 o;
        o.x = fmaf(1.5f, a0.x + a0.y, h.x);
        o.y = fmaf(1.5f, a1.x + a1.y, h.y);
        *(float2*)(op + c * HW) = o;
    }
}

// ---------------- launch ----------------
extern "C" void kernel_launch(void* const* d_in, const int* in_sizes, int n_in,
                              void* d_out, int out_size) {
    const float* hidden = (const float*)d_in[0];
    const float* emb    = (const float*)d_in[1];
    const float* bbox   = (const float*)d_in[2];
    const float* W1     = (const float*)d_in[3];
    const float* b1v    = (const float*)d_in[4];
    const float* W2     = (const float*)d_in[5];
    const float* b2v    = (const float*)d_in[6];
    float* outp = (float*)d_out;

    int B = in_sizes[0] / (C_DIM * HW);      // 8
    int M = B * N_ID;                        // 128 rows

    mlp1_kernel<<<dim3(C_DIM / 32, M / 32), 256>>>(emb, W1, b1v);
    mlp2_kernel<<<dim3(C_DIM / 32, M / 32), 256>>>(W2, b2v);
    norm_kernel<<<M, 128>>>();

    cudaFuncSetAttribute(main_kernel, cudaFuncAttributeMaxDynamicSharedMemorySize,
                         C_DIM * N_ID * (int)sizeof(float));
    main_kernel<<<B * BLKS_PER_BATCH, 256, C_DIM * N_ID * sizeof(float)>>>(hidden, bbox, outp);
}